// round 1
// baseline (speedup 1.0000x reference)
#include <cuda_runtime.h>
#include <math.h>

#define NB 2048   // batch
#define NF 512    // features
#define NH 256    // hidden
#define NE 64     // experts
#define NK 8      // top-k

// ---------------- scratch (no allocation allowed) ----------------
__device__ int   g_counts[NE];
__device__ int   g_tok[NE * NB];
__device__ float g_wt[NE * NB];
__device__ float g_escale[NE];   // trust * staleness
__device__ float g_efinv[NE];    // 1/max(||expert_features_e||, 1e-8)

// ---------------- kernel 0: per-expert scalars + count reset ----------------
__global__ void init_kernel(const float* __restrict__ ef,
                            const float* __restrict__ trust,
                            const float* __restrict__ dt) {
    int e = threadIdx.x;
    if (e < NE) {
        g_counts[e] = 0;
        g_escale[e] = trust[e] * fmaxf(0.1f, expf(-0.005f * dt[e]));
        const float4* r = (const float4*)(ef + e * NF);
        float s = 0.f;
        #pragma unroll 8
        for (int i = 0; i < NF / 4; i++) {
            float4 v = r[i];
            s += v.x * v.x + v.y * v.y + v.z * v.z + v.w * v.w;
        }
        g_efinv[e] = 1.0f / fmaxf(sqrtf(s), 1e-8f);
    }
}

// ---------------- kernel 1: zero output (poisoned by harness) ----------------
__global__ void zero_kernel(float4* __restrict__ out) {
    out[blockIdx.x * 256 + threadIdx.x] = make_float4(0.f, 0.f, 0.f, 0.f);
}

// ---------------- kernel 2: routing (16 tokens / block) ----------------
// smem: xs[16][516] (padded) | buf = max(pws[32][260], hs[16][256]+sc[16][68]+xinv[16])
#define XS_STRIDE 516
#define PW_STRIDE 260
#define SC_STRIDE 68
#define ROUT_SMEM ((16 * XS_STRIDE + 32 * PW_STRIDE) * 4)

__global__ void __launch_bounds__(256, 1)
routing_kernel(const float* __restrict__ feat, const float* __restrict__ pw,
               const float* __restrict__ pb,   const float* __restrict__ emb,
               const float* __restrict__ ef) {
    extern __shared__ float sm[];
    float* xs   = sm;                       // 16*516
    float* buf  = sm + 16 * XS_STRIDE;
    float* pws  = buf;                      // 32*260
    float* hs   = buf;                      // 16*256 (reuses pws region)
    float* sc   = buf + 16 * 256;           // 16*68
    float* xinv = buf + 16 * 256 + 16 * SC_STRIDE; // 16

    const int tid = threadIdx.x;
    const int t0  = blockIdx.x * 16;

    // ---- load X tile [16][512] (coalesced float4) ----
    #pragma unroll
    for (int i = 0; i < 8; i++) {
        int idx = tid + 256 * i;            // 0..2047
        int t   = idx >> 7;
        int k4  = (idx & 127) * 4;
        float4 v = *(const float4*)(feat + (size_t)(t0 + t) * NF + k4);
        *(float4*)(xs + t * XS_STRIDE + k4) = v;
    }
    __syncthreads();

    // ---- phase 1: h[16][256] = X @ pw^T ----
    const int t  = tid & 15;
    const int cg = tid >> 4;                // 16 col-groups of 16 cols
    float acc[16];
    #pragma unroll
    for (int c = 0; c < 16; c++) acc[c] = 0.f;

    for (int k0 = 0; k0 < NF; k0 += 32) {
        // stage pw tile: [256 cols][32 k] -> pws[kk][j]
        #pragma unroll
        for (int i = 0; i < 8; i++) {
            int j  = (tid >> 3) + i * 32;
            int kk = (tid & 7) * 4;
            float4 v = *(const float4*)(pw + (size_t)j * NF + k0 + kk);
            pws[(kk + 0) * PW_STRIDE + j] = v.x;
            pws[(kk + 1) * PW_STRIDE + j] = v.y;
            pws[(kk + 2) * PW_STRIDE + j] = v.z;
            pws[(kk + 3) * PW_STRIDE + j] = v.w;
        }
        __syncthreads();
        #pragma unroll
        for (int kk = 0; kk < 32; kk++) {
            float xv = xs[t * XS_STRIDE + k0 + kk];
            const float* wr = pws + kk * PW_STRIDE + cg * 16;
            #pragma unroll
            for (int c4 = 0; c4 < 4; c4++) {
                float4 w4 = *(const float4*)(wr + c4 * 4);
                acc[c4 * 4 + 0] += xv * w4.x;
                acc[c4 * 4 + 1] += xv * w4.y;
                acc[c4 * 4 + 2] += xv * w4.z;
                acc[c4 * 4 + 3] += xv * w4.w;
            }
        }
        __syncthreads();
    }

    // ---- write h (+bias) into hs (aliases pws; last loop iter ended with sync) ----
    #pragma unroll
    for (int c4 = 0; c4 < 4; c4++) {
        float4 hv;
        int jb = cg * 16 + c4 * 4;
        hv.x = acc[c4 * 4 + 0] + pb[jb + 0];
        hv.y = acc[c4 * 4 + 1] + pb[jb + 1];
        hv.z = acc[c4 * 4 + 2] + pb[jb + 2];
        hv.w = acc[c4 * 4 + 3] + pb[jb + 3];
        *(float4*)(hs + t * 256 + jb) = hv;
    }
    // ---- per-token inverse norm ----
    if (tid < 16) {
        const float* xr = xs + tid * XS_STRIDE;
        float s = 0.f;
        #pragma unroll 8
        for (int i = 0; i < NF / 4; i++) {
            float4 v = *(const float4*)(xr + i * 4);
            s += v.x * v.x + v.y * v.y + v.z * v.z + v.w * v.w;
        }
        xinv[tid] = 1.0f / fmaxf(sqrtf(s), 1e-8f);
    }
    __syncthreads();

    // ---- phase 2: score[t][e] for 1024 (t,e) pairs; lanes share e-rows ----
    #pragma unroll
    for (int i = 0; i < 4; i++) {
        int p  = tid + 256 * i;             // 0..1023
        int e  = p >> 4;                    // warp: 2 distinct e rows (coalesced LDG)
        int tt = p & 15;
        // gate logit: hs[tt] . emb[e] / 16
        float dg = 0.f;
        const float* hr = hs + tt * 256;
        const float* er = emb + (size_t)e * NH;
        #pragma unroll 8
        for (int j = 0; j < NH / 4; j++) {
            float4 a = *(const float4*)(hr + j * 4);
            float4 b = *(const float4*)(er + j * 4);
            dg += a.x * b.x + a.y * b.y + a.z * b.z + a.w * b.w;
        }
        float gate = 1.0f / (1.0f + expf(-dg * 0.0625f));
        // cosine sim
        float ds = 0.f;
        const float* xr = xs + tt * XS_STRIDE;
        const float* fr = ef + (size_t)e * NF;
        #pragma unroll 8
        for (int j = 0; j < NF / 4; j++) {
            float4 a = *(const float4*)(xr + j * 4);
            float4 b = *(const float4*)(fr + j * 4);
            ds += a.x * b.x + a.y * b.y + a.z * b.z + a.w * b.w;
        }
        float sim = fmaxf(ds * xinv[tt] * g_efinv[e], 0.f);
        sc[tt * SC_STRIDE + e] = gate * sim * g_escale[e];
    }
    __syncthreads();

    // ---- top-8 + softmax + scatter to expert lists ----
    if (tid < 16) {
        float* row = sc + tid * SC_STRIDE;
        float v[NK]; int ix[NK];
        #pragma unroll
        for (int k = 0; k < NK; k++) {
            float best = -1.f; int bi = 0;
            for (int e = 0; e < NE; e++) {
                float s = row[e];
                if (s > best) { best = s; bi = e; }
            }
            v[k] = best; ix[k] = bi; row[bi] = -1e30f;
        }
        float m = v[0], sum = 0.f, w[NK];
        #pragma unroll
        for (int k = 0; k < NK; k++) { w[k] = expf(v[k] - m); sum += w[k]; }
        float inv = 1.0f / sum;
        int tok = t0 + tid;
        #pragma unroll
        for (int k = 0; k < NK; k++) {
            int e = ix[k];
            int slot = atomicAdd(&g_counts[e], 1);
            g_tok[e * NB + slot] = tok;
            g_wt[e * NB + slot]  = w[k] * inv;
        }
    }
}

// ---------------- kernel 3: grouped MoE GEMM, fp32 ----------------
// grid (4 col-tiles of 128, 64 experts, 64 token-tiles of 32); block 256 thr
// thread computes 4 tokens x 4 cols
__global__ void __launch_bounds__(256, 2)
moe_gemm(const float* __restrict__ feat, const float* __restrict__ fw,
         const float* __restrict__ fb, float* __restrict__ out) {
    const int e    = blockIdx.y;
    const int g0   = blockIdx.x * 128;
    const int tile = blockIdx.z;
    const int cnt  = g_counts[e];
    if (tile * 32 >= cnt) return;

    __shared__ float xsT[32][32];   // [kk][token]
    __shared__ float ws[32][128];   // [kk][col]
    __shared__ int   toks[32];
    __shared__ float wts[32];

    const int tid = threadIdx.x;
    if (tid < 32) {
        int s = tile * 32 + tid;
        if (s < cnt) { toks[tid] = g_tok[e * NB + s]; wts[tid] = g_wt[e * NB + s]; }
        else         { toks[tid] = -1;                wts[tid] = 0.f; }
    }
    __syncthreads();

    const int tg = tid >> 5;   // token group 0..7 -> tokens tg*4..+3
    const int cg = tid & 31;   // col group   0..31 -> cols  cg*4..+3
    float a00=0,a01=0,a02=0,a03=0, a10=0,a11=0,a12=0,a13=0;
    float a20=0,a21=0,a22=0,a23=0, a30=0,a31=0,a32=0,a33=0;

    const float* wbase = fw + (size_t)e * NF * NF + g0;

    for (int k0 = 0; k0 < NF; k0 += 32) {
        // stage X: 32 tokens x 32 k
        {
            int tt = tid >> 3;
            int kk = (tid & 7) * 4;
            int tok = toks[tt];
            float4 v = make_float4(0.f, 0.f, 0.f, 0.f);
            if (tok >= 0) v = *(const float4*)(feat + (size_t)tok * NF + k0 + kk);
            xsT[kk + 0][tt] = v.x;
            xsT[kk + 1][tt] = v.y;
            xsT[kk + 2][tt] = v.z;
            xsT[kk + 3][tt] = v.w;
        }
        // stage W: 32 rows x 128 cols
        #pragma unroll
        for (int i = 0; i < 4; i++) {
            int r = (tid >> 5) + i * 8;
            int c = (tid & 31) * 4;
            *(float4*)&ws[r][c] = *(const float4*)(wbase + (size_t)(k0 + r) * NF + c);
        }
        __syncthreads();
        #pragma unroll
        for (int kk = 0; kk < 32; kk++) {
            float4 xq = *(const float4*)&xsT[kk][tg * 4];
            float4 wq = *(const float4*)&ws[kk][cg * 4];
            a00 += xq.x * wq.x; a01 += xq.x * wq.y; a02 += xq.x * wq.z; a03 += xq.x * wq.w;
            a10 += xq.y * wq.x; a11 += xq.y * wq.y; a12 += xq.y * wq.z; a13 += xq.y * wq.w;
            a20 += xq.z * wq.x; a21 += xq.z * wq.y; a22 += xq.z * wq.z; a23 += xq.z * wq.w;
            a30 += xq.w * wq.x; a31 += xq.w * wq.y; a32 += xq.w * wq.z; a33 += xq.w * wq.w;
        }
        __syncthreads();
    }

    // epilogue: out[tok][g] += wt * (acc + b[g])
    float4 b4 = *(const float4*)(fb + (size_t)e * NF + g0 + cg * 4);
    float accs[4][4] = {{a00,a01,a02,a03},{a10,a11,a12,a13},
                        {a20,a21,a22,a23},{a30,a31,a32,a33}};
    #pragma unroll
    for (int i = 0; i < 4; i++) {
        int tt = tg * 4 + i;
        int tok = toks[tt];
        if (tok < 0) continue;
        float wt = wts[tt];
        float* orow = out + (size_t)tok * NF + g0 + cg * 4;
        atomicAdd(orow + 0, wt * (accs[i][0] + b4.x));
        atomicAdd(orow + 1, wt * (accs[i][1] + b4.y));
        atomicAdd(orow + 2, wt * (accs[i][2] + b4.z));
        atomicAdd(orow + 3, wt * (accs[i][3] + b4.w));
    }
}

// ---------------- launch ----------------
extern "C" void kernel_launch(void* const* d_in, const int* in_sizes, int n_in,
                              void* d_out, int out_size) {
    const float* feat  = (const float*)d_in[0];  // [B,F]
    const float* pw    = (const float*)d_in[1];  // [H,F]
    const float* pb    = (const float*)d_in[2];  // [H]
    const float* emb   = (const float*)d_in[3];  // [E,H]
    const float* ef    = (const float*)d_in[4];  // [E,F]
    const float* trust = (const float*)d_in[5];  // [E]
    const float* dt    = (const float*)d_in[6];  // [E]
    const float* fw    = (const float*)d_in[7];  // [E,F,F]
    const float* fb    = (const float*)d_in[8];  // [E,F]
    float* out = (float*)d_out;

    static bool attr_done = false;
    if (!attr_done) {
        cudaFuncSetAttribute(routing_kernel,
                             cudaFuncAttributeMaxDynamicSharedMemorySize, ROUT_SMEM);
        attr_done = true;
    }

    init_kernel<<<1, 64>>>(ef, trust, dt);
    zero_kernel<<<(NB * NF) / (256 * 4), 256>>>((float4*)out);
    routing_kernel<<<NB / 16, 256, ROUT_SMEM>>>(feat, pw, pb, emb, ef);
    moe_gemm<<<dim3(4, NE, NB / 32), 256>>>(feat, fw, fb, out);
}

// round 2
// speedup vs baseline: 1.0050x; 1.0050x over previous
#include <cuda_runtime.h>
#include <math.h>

#define NB 2048   // batch
#define NF 512    // features
#define NH 256    // hidden
#define NE 64     // experts
#define NK 8      // top-k

typedef unsigned long long u64;

// ---------------- scratch (no allocation allowed) ----------------
__device__ int   g_counts[NE];
__device__ int   g_tok[NE * NB];
__device__ float g_wt[NE * NB];
__device__ float g_escale[NE];   // trust * staleness
__device__ float g_efinv[NE];    // 1/max(||expert_features_e||, 1e-8)

// ---------------- f32x2 helpers (Blackwell packed fp32) ----------------
__device__ __forceinline__ void fma2(u64& acc, u64 a, u64 b) {
    asm("fma.rn.f32x2 %0, %1, %2, %0;" : "+l"(acc) : "l"(a), "l"(b));
}
__device__ __forceinline__ u64 pack_dup(float x) {
    u64 p;
    asm("mov.b64 %0, {%1, %1};" : "=l"(p) : "f"(x));
    return p;
}
__device__ __forceinline__ float2 unpack2(u64 v) {
    float2 r;
    asm("mov.b64 {%0, %1}, %2;" : "=f"(r.x), "=f"(r.y) : "l"(v));
    return r;
}

// ---------------- kernel 0: per-expert scalars + count reset ----------------
__global__ void init_kernel(const float* __restrict__ ef,
                            const float* __restrict__ trust,
                            const float* __restrict__ dt) {
    int e = threadIdx.x;
    if (e < NE) {
        g_counts[e] = 0;
        g_escale[e] = trust[e] * fmaxf(0.1f, expf(-0.005f * dt[e]));
        const float4* r = (const float4*)(ef + e * NF);
        float s = 0.f;
        #pragma unroll 8
        for (int i = 0; i < NF / 4; i++) {
            float4 v = r[i];
            s += v.x * v.x + v.y * v.y + v.z * v.z + v.w * v.w;
        }
        g_efinv[e] = 1.0f / fmaxf(sqrtf(s), 1e-8f);
    }
}

// ---------------- kernel 1: zero output (poisoned by harness) ----------------
__global__ void zero_kernel(float4* __restrict__ out) {
    out[blockIdx.x * 256 + threadIdx.x] = make_float4(0.f, 0.f, 0.f, 0.f);
}

// ---------------- kernel 2: routing (16 tokens / block) ----------------
#define XS_STRIDE 516
#define PW_STRIDE 260
#define SC_STRIDE 68
#define ROUT_SMEM ((16 * XS_STRIDE + 32 * PW_STRIDE) * 4)

__global__ void __launch_bounds__(256, 1)
routing_kernel(const float* __restrict__ feat, const float* __restrict__ pw,
               const float* __restrict__ pb,   const float* __restrict__ emb,
               const float* __restrict__ ef) {
    extern __shared__ float sm[];
    float* xs   = sm;                       // 16*516
    float* buf  = sm + 16 * XS_STRIDE;
    float* pws  = buf;                      // 32*260
    float* hs   = buf;                      // 16*256 (reuses pws region)
    float* sc   = buf + 16 * 256;           // 16*68
    float* xinv = buf + 16 * 256 + 16 * SC_STRIDE; // 16

    const int tid = threadIdx.x;
    const int t0  = blockIdx.x * 16;

    #pragma unroll
    for (int i = 0; i < 8; i++) {
        int idx = tid + 256 * i;
        int t   = idx >> 7;
        int k4  = (idx & 127) * 4;
        float4 v = *(const float4*)(feat + (size_t)(t0 + t) * NF + k4);
        *(float4*)(xs + t * XS_STRIDE + k4) = v;
    }
    __syncthreads();

    const int t  = tid & 15;
    const int cg = tid >> 4;
    float acc[16];
    #pragma unroll
    for (int c = 0; c < 16; c++) acc[c] = 0.f;

    for (int k0 = 0; k0 < NF; k0 += 32) {
        #pragma unroll
        for (int i = 0; i < 8; i++) {
            int j  = (tid >> 3) + i * 32;
            int kk = (tid & 7) * 4;
            float4 v = *(const float4*)(pw + (size_t)j * NF + k0 + kk);
            pws[(kk + 0) * PW_STRIDE + j] = v.x;
            pws[(kk + 1) * PW_STRIDE + j] = v.y;
            pws[(kk + 2) * PW_STRIDE + j] = v.z;
            pws[(kk + 3) * PW_STRIDE + j] = v.w;
        }
        __syncthreads();
        #pragma unroll
        for (int kk = 0; kk < 32; kk++) {
            float xv = xs[t * XS_STRIDE + k0 + kk];
            const float* wr = pws + kk * PW_STRIDE + cg * 16;
            #pragma unroll
            for (int c4 = 0; c4 < 4; c4++) {
                float4 w4 = *(const float4*)(wr + c4 * 4);
                acc[c4 * 4 + 0] += xv * w4.x;
                acc[c4 * 4 + 1] += xv * w4.y;
                acc[c4 * 4 + 2] += xv * w4.z;
                acc[c4 * 4 + 3] += xv * w4.w;
            }
        }
        __syncthreads();
    }

    #pragma unroll
    for (int c4 = 0; c4 < 4; c4++) {
        float4 hv;
        int jb = cg * 16 + c4 * 4;
        hv.x = acc[c4 * 4 + 0] + pb[jb + 0];
        hv.y = acc[c4 * 4 + 1] + pb[jb + 1];
        hv.z = acc[c4 * 4 + 2] + pb[jb + 2];
        hv.w = acc[c4 * 4 + 3] + pb[jb + 3];
        *(float4*)(hs + t * 256 + jb) = hv;
    }
    if (tid < 16) {
        const float* xr = xs + tid * XS_STRIDE;
        float s = 0.f;
        #pragma unroll 8
        for (int i = 0; i < NF / 4; i++) {
            float4 v = *(const float4*)(xr + i * 4);
            s += v.x * v.x + v.y * v.y + v.z * v.z + v.w * v.w;
        }
        xinv[tid] = 1.0f / fmaxf(sqrtf(s), 1e-8f);
    }
    __syncthreads();

    #pragma unroll
    for (int i = 0; i < 4; i++) {
        int p  = tid + 256 * i;
        int e  = p >> 4;
        int tt = p & 15;
        float dg = 0.f;
        const float* hr = hs + tt * 256;
        const float* er = emb + (size_t)e * NH;
        #pragma unroll 8
        for (int j = 0; j < NH / 4; j++) {
            float4 a = *(const float4*)(hr + j * 4);
            float4 b = *(const float4*)(er + j * 4);
            dg += a.x * b.x + a.y * b.y + a.z * b.z + a.w * b.w;
        }
        float gate = 1.0f / (1.0f + expf(-dg * 0.0625f));
        float ds = 0.f;
        const float* xr = xs + tt * XS_STRIDE;
        const float* fr = ef + (size_t)e * NF;
        #pragma unroll 8
        for (int j = 0; j < NF / 4; j++) {
            float4 a = *(const float4*)(xr + j * 4);
            float4 b = *(const float4*)(fr + j * 4);
            ds += a.x * b.x + a.y * b.y + a.z * b.z + a.w * b.w;
        }
        float sim = fmaxf(ds * xinv[tt] * g_efinv[e], 0.f);
        sc[tt * SC_STRIDE + e] = gate * sim * g_escale[e];
    }
    __syncthreads();

    if (tid < 16) {
        float* row = sc + tid * SC_STRIDE;
        float v[NK]; int ix[NK];
        #pragma unroll
        for (int k = 0; k < NK; k++) {
            float best = -1.f; int bi = 0;
            for (int e = 0; e < NE; e++) {
                float s = row[e];
                if (s > best) { best = s; bi = e; }
            }
            v[k] = best; ix[k] = bi; row[bi] = -1e30f;
        }
        float m = v[0], sum = 0.f, w[NK];
        #pragma unroll
        for (int k = 0; k < NK; k++) { w[k] = expf(v[k] - m); sum += w[k]; }
        float inv = 1.0f / sum;
        int tok = t0 + tid;
        #pragma unroll
        for (int k = 0; k < NK; k++) {
            int e = ix[k];
            int slot = atomicAdd(&g_counts[e], 1);
            g_tok[e * NB + slot] = tok;
            g_wt[e * NB + slot]  = w[k] * inv;
        }
    }
}

// ---------------- kernel 3: grouped MoE GEMM, fp32 via f32x2 ----------------
// Block tile: 128 tokens x 128 cols, BK=16, 256 threads, 8x8 per thread.
// X stored duplicated in smem ([x,x] pairs) so packed operand = 1 LDS.128.
// Double-buffered smem, prefetch via registers.
//
// smem words: xd[2][16][256] = 8192 | ws[2][16][128] = 4096 | toks 128 | wts 128
#define GE_XD_WORDS   (2 * 16 * 256)
#define GE_WS_WORDS   (2 * 16 * 128)
#define GE_SMEM_BYTES ((GE_XD_WORDS + GE_WS_WORDS + 256) * 4)

__global__ void __launch_bounds__(256, 2)
moe_gemm(const float* __restrict__ feat, const float* __restrict__ fw,
         const float* __restrict__ fb, float* __restrict__ out) {
    const int e    = blockIdx.y;
    const int g0   = blockIdx.x * 128;
    const int tile = blockIdx.z;
    const int cnt  = g_counts[e];
    if (tile * 128 >= cnt) return;

    extern __shared__ float smg[];
    float* xd   = smg;                          // duplicated X: [2][16][256]
    float* wsm  = smg + GE_XD_WORDS;            // W: [2][16][128]
    int*   toks = (int*)(smg + GE_XD_WORDS + GE_WS_WORDS);
    float* wts  = (float*)(toks + 128);

    const int tid = threadIdx.x;

    // token list for this tile
    #pragma unroll
    for (int j = 0; j < 1; j++) {
        if (tid < 128) {
            int s = tile * 128 + tid;
            if (s < cnt) { toks[tid] = g_tok[e * NB + s]; wts[tid] = g_wt[e * NB + s]; }
            else         { toks[tid] = -1;                wts[tid] = 0.f; }
        }
    }
    __syncthreads();

    // per-thread staging slots
    const int xtok0 = tid & 127;            // j=0
    const int xkkg0 = tid >> 7;             // 0..1
    const int xtok1 = xtok0;                // j=1: idx = tid+256 -> same tok? no:
    // idx = tid + 256*j; tok = idx & 127; kkg = idx >> 7  (idx in [0,512))
    // j=0: kkg = tid>>7 in {0,1}; j=1: kkg = (tid+256)>>7 in {2,3}
    const int wrow0 = tid >> 5;             // j=0 row 0..7
    const int wcol0 = (tid & 31) * 4;
    const int wrow1 = wrow0 + 8;            // j=1 row 8..15

    const float* wbase = fw + (size_t)e * NF * NF + g0;

    const int gt0 = toks[xtok0];            // same token for both j (kkg differs)

    float4 vx0, vx1, vw0, vw1;
    // ---- prologue: load k0 = 0 ----
    {
        vx0 = make_float4(0.f,0.f,0.f,0.f);
        vx1 = vx0;
        if (gt0 >= 0) {
            vx0 = *(const float4*)(feat + (size_t)gt0 * NF + 0 + xkkg0 * 4);
            vx1 = *(const float4*)(feat + (size_t)gt0 * NF + 0 + (xkkg0 + 2) * 4);
        }
        vw0 = *(const float4*)(wbase + (size_t)(0 + wrow0) * NF + wcol0);
        vw1 = *(const float4*)(wbase + (size_t)(0 + wrow1) * NF + wcol0);
    }
    // store into buffer 0
    {
        float* xb = xd + (xkkg0 * 4) * 256 + 2 * xtok0;
        *(u64*)(xb + 0 * 256) = pack_dup(vx0.x);
        *(u64*)(xb + 1 * 256) = pack_dup(vx0.y);
        *(u64*)(xb + 2 * 256) = pack_dup(vx0.z);
        *(u64*)(xb + 3 * 256) = pack_dup(vx0.w);
        float* xb1 = xd + ((xkkg0 + 2) * 4) * 256 + 2 * xtok0;
        *(u64*)(xb1 + 0 * 256) = pack_dup(vx1.x);
        *(u64*)(xb1 + 1 * 256) = pack_dup(vx1.y);
        *(u64*)(xb1 + 2 * 256) = pack_dup(vx1.z);
        *(u64*)(xb1 + 3 * 256) = pack_dup(vx1.w);
        *(float4*)(wsm + wrow0 * 128 + wcol0) = vw0;
        *(float4*)(wsm + wrow1 * 128 + wcol0) = vw1;
    }
    __syncthreads();

    const int ty = tid >> 4;      // 0..15 token groups
    const int tx = tid & 15;      // 0..15 col groups

    u64 acc[8][4];
    #pragma unroll
    for (int m = 0; m < 8; m++)
        #pragma unroll
        for (int p = 0; p < 4; p++) acc[m][p] = 0ULL;

    for (int it = 0; it < NF / 16; it++) {
        const int buf  = it & 1;
        const int nbuf = buf ^ 1;
        // prefetch next stage to regs
        if (it + 1 < NF / 16) {
            int k0 = (it + 1) * 16;
            vx0 = make_float4(0.f,0.f,0.f,0.f);
            vx1 = vx0;
            if (gt0 >= 0) {
                vx0 = *(const float4*)(feat + (size_t)gt0 * NF + k0 + xkkg0 * 4);
                vx1 = *(const float4*)(feat + (size_t)gt0 * NF + k0 + (xkkg0 + 2) * 4);
            }
            vw0 = *(const float4*)(wbase + (size_t)(k0 + wrow0) * NF + wcol0);
            vw1 = *(const float4*)(wbase + (size_t)(k0 + wrow1) * NF + wcol0);
        }
        // compute on current buffer
        const float* xbuf = xd  + buf * 4096;
        const float* wbuf = wsm + buf * 2048;
        #pragma unroll
        for (int kk = 0; kk < 16; kk++) {
            const float* xr = xbuf + kk * 256;
            const float* wr = wbuf + kk * 128;
            ulonglong2 xa = *(const ulonglong2*)(xr + ty * 8);
            ulonglong2 xb = *(const ulonglong2*)(xr + ty * 8 + 4);
            ulonglong2 xc = *(const ulonglong2*)(xr + 128 + ty * 8);
            ulonglong2 xe = *(const ulonglong2*)(xr + 128 + ty * 8 + 4);
            ulonglong2 wa = *(const ulonglong2*)(wr + tx * 4);
            ulonglong2 wb = *(const ulonglong2*)(wr + 64 + tx * 4);
            u64 X[8] = {xa.x, xa.y, xb.x, xb.y, xc.x, xc.y, xe.x, xe.y};
            u64 W[4] = {wa.x, wa.y, wb.x, wb.y};
            #pragma unroll
            for (int m = 0; m < 8; m++) {
                #pragma unroll
                for (int p = 0; p < 4; p++) fma2(acc[m][p], X[m], W[p]);
            }
        }
        // store prefetched stage
        if (it + 1 < NF / 16) {
            float* xb = xd + nbuf * 4096 + (xkkg0 * 4) * 256 + 2 * xtok0;
            *(u64*)(xb + 0 * 256) = pack_dup(vx0.x);
            *(u64*)(xb + 1 * 256) = pack_dup(vx0.y);
            *(u64*)(xb + 2 * 256) = pack_dup(vx0.z);
            *(u64*)(xb + 3 * 256) = pack_dup(vx0.w);
            float* xb1 = xd + nbuf * 4096 + ((xkkg0 + 2) * 4) * 256 + 2 * xtok0;
            *(u64*)(xb1 + 0 * 256) = pack_dup(vx1.x);
            *(u64*)(xb1 + 1 * 256) = pack_dup(vx1.y);
            *(u64*)(xb1 + 2 * 256) = pack_dup(vx1.z);
            *(u64*)(xb1 + 3 * 256) = pack_dup(vx1.w);
            float* wsb = wsm + nbuf * 2048;
            *(float4*)(wsb + wrow0 * 128 + wcol0) = vw0;
            *(float4*)(wsb + wrow1 * 128 + wcol0) = vw1;
        }
        __syncthreads();
    }

    // ---- epilogue: out[tok][col] += wt * (acc + bias) ----
    float4 b0 = *(const float4*)(fb + (size_t)e * NF + g0 + tx * 4);
    float4 b1 = *(const float4*)(fb + (size_t)e * NF + g0 + 64 + tx * 4);
    float bias[8] = {b0.x, b0.y, b0.z, b0.w, b1.x, b1.y, b1.z, b1.w};

    #pragma unroll
    for (int m = 0; m < 8; m++) {
        int tt  = (m < 4) ? (ty * 4 + m) : (64 + ty * 4 + (m - 4));
        int tok = toks[tt];
        if (tok < 0) continue;
        float wt = wts[tt];
        float* orow = out + (size_t)tok * NF + g0;
        #pragma unroll
        for (int p = 0; p < 4; p++) {
            float2 a = unpack2(acc[m][p]);
            int h  = p >> 1;
            int c  = h * 64 + tx * 4 + (p & 1) * 2;
            int bi = h * 4 + (p & 1) * 2;
            atomicAdd(orow + c + 0, wt * (a.x + bias[bi + 0]));
            atomicAdd(orow + c + 1, wt * (a.y + bias[bi + 1]));
        }
    }
}

// ---------------- launch ----------------
extern "C" void kernel_launch(void* const* d_in, const int* in_sizes, int n_in,
                              void* d_out, int out_size) {
    const float* feat  = (const float*)d_in[0];  // [B,F]
    const float* pw    = (const float*)d_in[1];  // [H,F]
    const float* pb    = (const float*)d_in[2];  // [H]
    const float* emb   = (const float*)d_in[3];  // [E,H]
    const float* ef    = (const float*)d_in[4];  // [E,F]
    const float* trust = (const float*)d_in[5];  // [E]
    const float* dt    = (const float*)d_in[6];  // [E]
    const float* fw    = (const float*)d_in[7];  // [E,F,F]
    const float* fb    = (const float*)d_in[8];  // [E,F]
    float* out = (float*)d_out;

    static bool attr_done = false;
    if (!attr_done) {
        cudaFuncSetAttribute(routing_kernel,
                             cudaFuncAttributeMaxDynamicSharedMemorySize, ROUT_SMEM);
        cudaFuncSetAttribute(moe_gemm,
                             cudaFuncAttributeMaxDynamicSharedMemorySize, GE_SMEM_BYTES);
        attr_done = true;
    }

    init_kernel<<<1, 64>>>(ef, trust, dt);
    zero_kernel<<<(NB * NF) / (256 * 4), 256>>>((float4*)out);
    routing_kernel<<<NB / 16, 256, ROUT_SMEM>>>(feat, pw, pb, emb, ef);
    moe_gemm<<<dim3(4, NE, NB / 128), 256, GE_SMEM_BYTES>>>(feat, fw, fb, out);
}

// round 4
// speedup vs baseline: 1.3227x; 1.3161x over previous
#include <cuda_runtime.h>
#include <cuda_bf16.h>
#include <math.h>
#include <stdint.h>

#define NB 2048   // batch
#define NF 512    // features
#define NH 256    // hidden
#define NE 64     // experts
#define NK 8      // top-k

typedef unsigned int u32;

// ---------------- scratch (no allocation allowed) ----------------
__device__ int   g_counts[NE];
__device__ int   g_tok[NE * NB];
__device__ float g_wt[NE * NB];
__device__ float g_escale[NE];
__device__ float g_efinv[NE];
// bf16 hi/lo split buffers
__device__ __nv_bfloat16 g_xhi[NB * NF];               // 2MB
__device__ __nv_bfloat16 g_xlo[NB * NF];               // 2MB
__device__ __nv_bfloat16 g_wthi[(size_t)NE * NF * NF]; // 33.5MB, layout [e][n][k]
__device__ __nv_bfloat16 g_wtlo[(size_t)NE * NF * NF]; // 33.5MB

// ---------------- PTX helpers (sm_80-era; valid on sm_100 target) ----------
__device__ __forceinline__ uint32_t smem_to_u32(const void* p) {
    uint32_t a;
    asm("{ .reg .u64 t; cvta.to.shared.u64 t, %1; cvt.u32.u64 %0, t; }"
        : "=r"(a) : "l"(p));
    return a;
}
__device__ __forceinline__ void cp16(uint32_t dst, const void* src, int srcsize) {
    asm volatile("cp.async.cg.shared.global [%0], [%1], 16, %2;"
                 :: "r"(dst), "l"(src), "r"(srcsize));
}
#define CP_COMMIT() asm volatile("cp.async.commit_group;" ::: "memory")
#define CP_WAIT(n)  asm volatile("cp.async.wait_group %0;" :: "n"(n) : "memory")

__device__ __forceinline__ void ldm_x4(u32& r0, u32& r1, u32& r2, u32& r3, u32 addr) {
    asm volatile("ldmatrix.sync.aligned.m8n8.x4.shared.b16 {%0,%1,%2,%3}, [%4];"
                 : "=r"(r0), "=r"(r1), "=r"(r2), "=r"(r3) : "r"(addr));
}
__device__ __forceinline__ void mma_bf16(float& c0, float& c1, float& c2, float& c3,
                                         u32 a0, u32 a1, u32 a2, u32 a3,
                                         u32 b0, u32 b1) {
    asm volatile("mma.sync.aligned.m16n8k16.row.col.f32.bf16.bf16.f32 "
                 "{%0,%1,%2,%3}, {%4,%5,%6,%7}, {%8,%9}, {%0,%1,%2,%3};"
                 : "+f"(c0), "+f"(c1), "+f"(c2), "+f"(c3)
                 : "r"(a0), "r"(a1), "r"(a2), "r"(a3), "r"(b0), "r"(b1));
}

// ---------------- bf16 hi/lo split ----------------
__device__ __forceinline__ void split2(float a, float b, u32& hi, u32& lo) {
    __nv_bfloat16 ah = __float2bfloat16(a), bh = __float2bfloat16(b);
    float ar = a - __bfloat162float(ah);
    float br = b - __bfloat162float(bh);
    __nv_bfloat16 al = __float2bfloat16(ar), bl = __float2bfloat16(br);
    hi = (u32)__bfloat16_as_ushort(ah) | ((u32)__bfloat16_as_ushort(bh) << 16);
    lo = (u32)__bfloat16_as_ushort(al) | ((u32)__bfloat16_as_ushort(bl) << 16);
}

// ---------------- kernel 0: per-expert scalars + count reset ----------------
__global__ void init_kernel(const float* __restrict__ ef,
                            const float* __restrict__ trust,
                            const float* __restrict__ dt) {
    int e = threadIdx.x;
    if (e < NE) {
        g_counts[e] = 0;
        g_escale[e] = trust[e] * fmaxf(0.1f, expf(-0.005f * dt[e]));
        const float4* r = (const float4*)(ef + e * NF);
        float s = 0.f;
        #pragma unroll 8
        for (int i = 0; i < NF / 4; i++) {
            float4 v = r[i];
            s += v.x * v.x + v.y * v.y + v.z * v.z + v.w * v.w;
        }
        g_efinv[e] = 1.0f / fmaxf(sqrtf(s), 1e-8f);
    }
}

// ---------------- kernel 1: zero output ----------------
__global__ void zero_kernel(float4* __restrict__ out) {
    out[blockIdx.x * 256 + threadIdx.x] = make_float4(0.f, 0.f, 0.f, 0.f);
}

// ---------------- kernel 1b: convert X to bf16 hi/lo ----------------
__global__ void convert_x(const float* __restrict__ feat) {
    u32* xh = (u32*)g_xhi;
    u32* xl = (u32*)g_xlo;
    int p = blockIdx.x * 256 + threadIdx.x;
    const int npairs = NB * NF / 2;
    for (; p < npairs; p += gridDim.x * 256) {
        float2 v = *(const float2*)(feat + 2 * p);
        u32 hi, lo;
        split2(v.x, v.y, hi, lo);
        xh[p] = hi; xl[p] = lo;
    }
}

// ---------------- kernel 1c: convert + transpose W -> [e][n][k] bf16 hi/lo ----
__global__ void __launch_bounds__(256)
convert_w(const float* __restrict__ fw) {
    __shared__ float s[64][65];
    const int e  = blockIdx.z;
    const int k0 = blockIdx.x * 64;
    const int n0 = blockIdx.y * 64;
    const int tid = threadIdx.x;
    const float* src = fw + ((size_t)e * NF + k0) * NF + n0;
    #pragma unroll
    for (int i = 0; i < 16; i++) {
        int idx = tid + 256 * i;
        int kl = idx >> 6, nl = idx & 63;
        s[kl][nl] = src[(size_t)kl * NF + nl];
    }
    __syncthreads();
    u32* wh = (u32*)g_wthi;
    u32* wl = (u32*)g_wtlo;
    #pragma unroll
    for (int i = 0; i < 8; i++) {
        int idx = tid + 256 * i;
        int nl = idx >> 5;
        int kp = (idx & 31) * 2;
        float a = s[kp][nl], b = s[kp + 1][nl];
        u32 hi, lo;
        split2(a, b, hi, lo);
        size_t off = (((size_t)e * NF + n0 + nl) * NF + k0 + kp) >> 1;
        wh[off] = hi; wl[off] = lo;
    }
}

// ---------------- kernel 2: routing (unchanged) ----------------
#define XS_STRIDE 516
#define PW_STRIDE 260
#define SC_STRIDE 68
#define ROUT_SMEM ((16 * XS_STRIDE + 32 * PW_STRIDE) * 4)

__global__ void __launch_bounds__(256, 1)
routing_kernel(const float* __restrict__ feat, const float* __restrict__ pw,
               const float* __restrict__ pb,   const float* __restrict__ emb,
               const float* __restrict__ ef) {
    extern __shared__ float sm[];
    float* xs   = sm;
    float* buf  = sm + 16 * XS_STRIDE;
    float* pws  = buf;
    float* hs   = buf;
    float* sc   = buf + 16 * 256;
    float* xinv = buf + 16 * 256 + 16 * SC_STRIDE;

    const int tid = threadIdx.x;
    const int t0  = blockIdx.x * 16;

    #pragma unroll
    for (int i = 0; i < 8; i++) {
        int idx = tid + 256 * i;
        int t   = idx >> 7;
        int k4  = (idx & 127) * 4;
        float4 v = *(const float4*)(feat + (size_t)(t0 + t) * NF + k4);
        *(float4*)(xs + t * XS_STRIDE + k4) = v;
    }
    __syncthreads();

    const int t  = tid & 15;
    const int cg = tid >> 4;
    float acc[16];
    #pragma unroll
    for (int c = 0; c < 16; c++) acc[c] = 0.f;

    for (int k0 = 0; k0 < NF; k0 += 32) {
        #pragma unroll
        for (int i = 0; i < 8; i++) {
            int j  = (tid >> 3) + i * 32;
            int kk = (tid & 7) * 4;
            float4 v = *(const float4*)(pw + (size_t)j * NF + k0 + kk);
            pws[(kk + 0) * PW_STRIDE + j] = v.x;
            pws[(kk + 1) * PW_STRIDE + j] = v.y;
            pws[(kk + 2) * PW_STRIDE + j] = v.z;
            pws[(kk + 3) * PW_STRIDE + j] = v.w;
        }
        __syncthreads();
        #pragma unroll
        for (int kk = 0; kk < 32; kk++) {
            float xv = xs[t * XS_STRIDE + k0 + kk];
            const float* wr = pws + kk * PW_STRIDE + cg * 16;
            #pragma unroll
            for (int c4 = 0; c4 < 4; c4++) {
                float4 w4 = *(const float4*)(wr + c4 * 4);
                acc[c4 * 4 + 0] += xv * w4.x;
                acc[c4 * 4 + 1] += xv * w4.y;
                acc[c4 * 4 + 2] += xv * w4.z;
                acc[c4 * 4 + 3] += xv * w4.w;
            }
        }
        __syncthreads();
    }

    #pragma unroll
    for (int c4 = 0; c4 < 4; c4++) {
        float4 hv;
        int jb = cg * 16 + c4 * 4;
        hv.x = acc[c4 * 4 + 0] + pb[jb + 0];
        hv.y = acc[c4 * 4 + 1] + pb[jb + 1];
        hv.z = acc[c4 * 4 + 2] + pb[jb + 2];
        hv.w = acc[c4 * 4 + 3] + pb[jb + 3];
        *(float4*)(hs + t * 256 + jb) = hv;
    }
    if (tid < 16) {
        const float* xr = xs + tid * XS_STRIDE;
        float s = 0.f;
        #pragma unroll 8
        for (int i = 0; i < NF / 4; i++) {
            float4 v = *(const float4*)(xr + i * 4);
            s += v.x * v.x + v.y * v.y + v.z * v.z + v.w * v.w;
        }
        xinv[tid] = 1.0f / fmaxf(sqrtf(s), 1e-8f);
    }
    __syncthreads();

    #pragma unroll
    for (int i = 0; i < 4; i++) {
        int p  = tid + 256 * i;
        int e  = p >> 4;
        int tt = p & 15;
        float dg = 0.f;
        const float* hr = hs + tt * 256;
        const float* er = emb + (size_t)e * NH;
        #pragma unroll 8
        for (int j = 0; j < NH / 4; j++) {
            float4 a = *(const float4*)(hr + j * 4);
            float4 b = *(const float4*)(er + j * 4);
            dg += a.x * b.x + a.y * b.y + a.z * b.z + a.w * b.w;
        }
        float gate = 1.0f / (1.0f + expf(-dg * 0.0625f));
        float ds = 0.f;
        const float* xr = xs + tt * XS_STRIDE;
        const float* fr = ef + (size_t)e * NF;
        #pragma unroll 8
        for (int j = 0; j < NF / 4; j++) {
            float4 a = *(const float4*)(xr + j * 4);
            float4 b = *(const float4*)(fr + j * 4);
            ds += a.x * b.x + a.y * b.y + a.z * b.z + a.w * b.w;
        }
        float sim = fmaxf(ds * xinv[tt] * g_efinv[e], 0.f);
        sc[tt * SC_STRIDE + e] = gate * sim * g_escale[e];
    }
    __syncthreads();

    if (tid < 16) {
        float* row = sc + tid * SC_STRIDE;
        float v[NK]; int ix[NK];
        #pragma unroll
        for (int k = 0; k < NK; k++) {
            float best = -1.f; int bi = 0;
            for (int e = 0; e < NE; e++) {
                float s = row[e];
                if (s > best) { best = s; bi = e; }
            }
            v[k] = best; ix[k] = bi; row[bi] = -1e30f;
        }
        float m = v[0], sum = 0.f, w[NK];
        #pragma unroll
        for (int k = 0; k < NK; k++) { w[k] = expf(v[k] - m); sum += w[k]; }
        float inv = 1.0f / sum;
        int tok = t0 + tid;
        #pragma unroll
        for (int k = 0; k < NK; k++) {
            int e = ix[k];
            int slot = atomicAdd(&g_counts[e], 1);
            g_tok[e * NB + slot] = tok;
            g_wt[e * NB + slot]  = w[k] * inv;
        }
    }
}

// ---------------- kernel 3: mma.sync bf16 hi/lo grouped MoE GEMM ----------
// CTA tile: M=128 gathered tokens x N=128 cols. K chunks of 64, cp.async
// double-buffered. 8 warps as 2(M) x 4(N); warp tile 64x32.
// 3 passes per k16: Ahi*Bhi + Ahi*Blo + Alo*Bhi, fp32 accum in regs.
#define MG_DATA    1024
#define MG_BUF     65536
#define MG_AHI     0
#define MG_ALO     16384
#define MG_BHI     32768
#define MG_BLO     49152
#define MG_SMEM    (MG_DATA + 2 * MG_BUF)   // 132096 bytes

__global__ void __launch_bounds__(256, 1)
moe_gemm_mma(const float* __restrict__ fb, float* __restrict__ out) {
    const int e    = blockIdx.y;
    const int n0   = blockIdx.x * 128;
    const int tile = blockIdx.z;
    const int cnt  = g_counts[e];
    if (tile * 128 >= cnt) return;

    extern __shared__ char smem[];
    const uint32_t sb = smem_to_u32(smem);
    const int tid = threadIdx.x;

    int*   toks = (int*)(smem);
    float* wts  = (float*)(smem + 512);
    {
        int s = tile * 128 + tid;
        if (tid < 128) {
            if (s < cnt) { toks[tid] = g_tok[e * NB + s]; wts[tid] = g_wt[e * NB + s]; }
            else         { toks[tid] = -1;                wts[tid] = 0.f; }
        }
    }
    __syncthreads();

    // ---- staging mapping: 2 threads per row; each stages 4 u4 (64B) ----
    const int srow  = tid >> 1;
    const int spart = (tid & 1) * 4;
    const int stok  = toks[srow];
    const int asz   = (stok >= 0) ? 16 : 0;
    const uint4* aH = (const uint4*)(g_xhi + (size_t)max(stok, 0) * NF);
    const uint4* aL = (const uint4*)(g_xlo + (size_t)max(stok, 0) * NF);
    const uint4* bH = (const uint4*)(g_wthi + ((size_t)e * NF + n0 + srow) * NF);
    const uint4* bL = (const uint4*)(g_wtlo + ((size_t)e * NF + n0 + srow) * NF);
    const uint32_t srowb = sb + MG_DATA + srow * 128;
    const int      ssw   = (srow & 7) * 16;

    #define PREFETCH(c)                                                          \
    do {                                                                         \
        const int _buf = (c) & 1;                                                \
        const uint32_t _d = srowb + _buf * MG_BUF;                               \
        _Pragma("unroll")                                                        \
        for (int j = 0; j < 4; j++) {                                            \
            const int c16 = spart + j;                                           \
            const uint32_t off = (uint32_t)((c16 * 16) ^ ssw);                   \
            cp16(_d + MG_AHI + off, aH + (c) * 8 + c16, asz);                    \
            cp16(_d + MG_ALO + off, aL + (c) * 8 + c16, asz);                    \
            cp16(_d + MG_BHI + off, bH + (c) * 8 + c16, 16);                     \
            cp16(_d + MG_BLO + off, bL + (c) * 8 + c16, 16);                     \
        }                                                                        \
    } while (0)

    PREFETCH(0);
    CP_COMMIT();

    const int lid = tid & 31;
    const int wid = tid >> 5;
    const int wm  = wid & 1;       // 2 m-groups of 64
    const int wn  = wid >> 1;      // 4 n-groups of 32

    float acc[4][4][4];
    #pragma unroll
    for (int mt = 0; mt < 4; mt++)
        #pragma unroll
        for (int nt = 0; nt < 4; nt++)
            #pragma unroll
            for (int q = 0; q < 4; q++) acc[mt][nt][q] = 0.f;

    // fragment lane addressing (canonical ldmatrix x4)
    const int fa_row = (lid & 15);      // + tile base
    const int fa_hi  = (lid >> 4);      // 0/1 -> +16B col

    for (int c = 0; c < 8; c++) {
        if (c < 7) { PREFETCH(c + 1); CP_COMMIT(); CP_WAIT(1); }
        else       { CP_WAIT(0); }
        __syncthreads();

        const uint32_t base = sb + MG_DATA + (c & 1) * MG_BUF;

        #pragma unroll
        for (int ks = 0; ks < 4; ks++) {
            const int c16 = ks * 2 + fa_hi;
            // A fragments (hi & lo): 4 m-tiles
            u32 ah[4][4], al[4][4];
            #pragma unroll
            for (int mt = 0; mt < 4; mt++) {
                const int r = wm * 64 + mt * 16 + fa_row;
                const uint32_t off = r * 128 + (uint32_t)((c16 * 16) ^ ((r & 7) * 16));
                ldm_x4(ah[mt][0], ah[mt][1], ah[mt][2], ah[mt][3], base + MG_AHI + off);
                ldm_x4(al[mt][0], al[mt][1], al[mt][2], al[mt][3], base + MG_ALO + off);
            }
            // B fragments (hi & lo): 2 x4 loads cover 4 n-tiles
            u32 bh[2][4], bl[2][4];
            #pragma unroll
            for (int p = 0; p < 2; p++) {
                const int r = wn * 32 + p * 16 + fa_row;
                const uint32_t off = r * 128 + (uint32_t)((c16 * 16) ^ ((r & 7) * 16));
                ldm_x4(bh[p][0], bh[p][1], bh[p][2], bh[p][3], base + MG_BHI + off);
                ldm_x4(bl[p][0], bl[p][1], bl[p][2], bl[p][3], base + MG_BLO + off);
            }
            // 3 passes x 16 mma
            #pragma unroll
            for (int mt = 0; mt < 4; mt++) {
                #pragma unroll
                for (int nt = 0; nt < 4; nt++) {
                    const int p = nt >> 1, h = nt & 1;   // frag select
                    float* cc = acc[mt][nt];
                    mma_bf16(cc[0], cc[1], cc[2], cc[3],
                             ah[mt][0], ah[mt][1], ah[mt][2], ah[mt][3],
                             bh[p][h], bh[p][h + 2]);
                    mma_bf16(cc[0], cc[1], cc[2], cc[3],
                             ah[mt][0], ah[mt][1], ah[mt][2], ah[mt][3],
                             bl[p][h], bl[p][h + 2]);
                    mma_bf16(cc[0], cc[1], cc[2], cc[3],
                             al[mt][0], al[mt][1], al[mt][2], al[mt][3],
                             bh[p][h], bh[p][h + 2]);
                }
            }
        }
        __syncthreads();
    }

    // ---- epilogue: out[tok][n] += wt * (acc + bias) ----
    const float* fbr = fb + (size_t)e * NF + n0;
    #pragma unroll
    for (int mt = 0; mt < 4; mt++) {
        const int r0 = wm * 64 + mt * 16 + (lid >> 2);
        const int r1 = r0 + 8;
        const int tok0 = toks[r0], tok1 = toks[r1];
        const float w0 = wts[r0],  w1 = wts[r1];
        #pragma unroll
        for (int nt = 0; nt < 4; nt++) {
            const int cb = wn * 32 + nt * 8 + (lid & 3) * 2;
            const float b0v = fbr[cb], b1v = fbr[cb + 1];
            const float* cc = acc[mt][nt];
            if (tok0 >= 0) {
                float* orow = out + (size_t)tok0 * NF + n0 + cb;
                atomicAdd(orow + 0, w0 * (cc[0] + b0v));
                atomicAdd(orow + 1, w0 * (cc[1] + b1v));
            }
            if (tok1 >= 0) {
                float* orow = out + (size_t)tok1 * NF + n0 + cb;
                atomicAdd(orow + 0, w1 * (cc[2] + b0v));
                atomicAdd(orow + 1, w1 * (cc[3] + b1v));
            }
        }
    }
}

// ---------------- launch ----------------
extern "C" void kernel_launch(void* const* d_in, const int* in_sizes, int n_in,
                              void* d_out, int out_size) {
    const float* feat  = (const float*)d_in[0];  // [B,F]
    const float* pw    = (const float*)d_in[1];  // [H,F]
    const float* pb    = (const float*)d_in[2];  // [H]
    const float* emb   = (const float*)d_in[3];  // [E,H]
    const float* ef    = (const float*)d_in[4];  // [E,F]
    const float* trust = (const float*)d_in[5];  // [E]
    const float* dt    = (const float*)d_in[6];  // [E]
    const float* fw    = (const float*)d_in[7];  // [E,F,F]
    const float* fb    = (const float*)d_in[8];  // [E,F]
    float* out = (float*)d_out;

    static bool attr_done = false;
    if (!attr_done) {
        cudaFuncSetAttribute(routing_kernel,
                             cudaFuncAttributeMaxDynamicSharedMemorySize, ROUT_SMEM);
        cudaFuncSetAttribute(moe_gemm_mma,
                             cudaFuncAttributeMaxDynamicSharedMemorySize, MG_SMEM);
        attr_done = true;
    }

    init_kernel<<<1, 64>>>(ef, trust, dt);
    zero_kernel<<<(NB * NF) / (256 * 4), 256>>>((float4*)out);
    convert_x<<<512, 256>>>(feat);
    convert_w<<<dim3(8, 8, NE), 256>>>(fw);
    routing_kernel<<<NB / 16, 256, ROUT_SMEM>>>(feat, pw, pb, emb, ef);
    moe_gemm_mma<<<dim3(4, NE, NB / 128), 256, MG_SMEM>>>(fb, out);
}